// round 1
// baseline (speedup 1.0000x reference)
#include <cuda_runtime.h>

#define NPTS 16384
#define CDIM 64
#define KNN  16
#define OUTC 256   // C*R = 64*4

__device__ float g_sq[NPTS];
__device__ int   g_idx[NPTS * KNN];
__device__ float g_A[NPTS * OUTC];
__device__ float g_B[NPTS * OUTC];

__device__ __forceinline__ float finf() { return __int_as_float(0x7f800000); }

// ---------------------------------------------------------------------------
// Kernel 1: squared norms. One warp per row (C=64 -> 2 loads/lane).
// ---------------------------------------------------------------------------
__global__ void sq_kernel(const float* __restrict__ x) {
    int w    = (blockIdx.x * blockDim.x + threadIdx.x) >> 5;
    int lane = threadIdx.x & 31;
    if (w < NPTS) {
        float v0 = x[w * CDIM + lane];
        float v1 = x[w * CDIM + 32 + lane];
        float s = v0 * v0 + v1 * v1;
        #pragma unroll
        for (int o = 16; o; o >>= 1) s += __shfl_xor_sync(0xffffffffu, s, o);
        if (lane == 0) g_sq[w] = s;
    }
}

// ---------------------------------------------------------------------------
// Kernel 2: A = x @ (W1 - W2) + b ; B = x @ W2
// W is (128, 256) row-major, W1 = rows [0,64), W2 = rows [64,128).
// Block: 256 threads (one per output col), 8 rows per block.
// ---------------------------------------------------------------------------
__global__ void gemmAB_kernel(const float* __restrict__ x,
                              const float* __restrict__ W,
                              const float* __restrict__ b) {
    __shared__ float xs[8][CDIM];
    int row0 = blockIdx.x * 8;
    int t = threadIdx.x;

    for (int e = t; e < 8 * CDIM; e += 256)
        xs[e >> 6][e & 63] = x[row0 * CDIM + e];
    __syncthreads();

    float accA[8], accB[8];
    #pragma unroll
    for (int r = 0; r < 8; ++r) { accA[r] = 0.f; accB[r] = 0.f; }

    #pragma unroll 4
    for (int c = 0; c < CDIM; ++c) {
        float w1 = W[c * OUTC + t];
        float w2 = W[(c + CDIM) * OUTC + t];
        float wd = w1 - w2;
        #pragma unroll
        for (int r = 0; r < 8; ++r) {
            float xv = xs[r][c];
            accA[r] += xv * wd;
            accB[r] += xv * w2;
        }
    }
    float bias = b[t];
    #pragma unroll
    for (int r = 0; r < 8; ++r) {
        g_A[(row0 + r) * OUTC + t] = accA[r] + bias;
        g_B[(row0 + r) * OUTC + t] = accB[r];
    }
}

// ---------------------------------------------------------------------------
// Kernel 3: fused gram-matrix + streaming top-K (smallest distances).
// Block: 128 threads (tx 0..15, ty 0..7), tile 64 rows x 64 cols.
// Distances compared as d' = sq[col] - 2*dot (monotone in true distance per row).
// Xc smem buffer is reused as the distance tile after the k-loop.
// Threads 0..63 each own one row's top-K list (in smem, threshold in register).
// ---------------------------------------------------------------------------
__global__ void __launch_bounds__(128) knn_kernel(const float* __restrict__ x) {
    __shared__ float Xr[CDIM][65];   // [k][r], transposed row tile
    __shared__ float Xc[CDIM][65];   // [k][c], transposed col tile; reused as dtile[r][c]
    __shared__ float skd[64][17];    // top-K distances per owned row
    __shared__ int   ski[64][17];    // top-K indices
    __shared__ float sqc[64];

    int t  = threadIdx.x;
    int tx = t & 15;        // 0..15 -> 4 cols each
    int ty = t >> 4;        // 0..7  -> 8 rows each
    int row0 = blockIdx.x * 64;

    // load row tile transposed (coalesced global, conflict-free smem: stride 65)
    for (int e = t; e < 64 * CDIM; e += 128) {
        int r = e >> 6, k = e & 63;
        Xr[k][r] = x[(row0 + r) * CDIM + k];
    }
    if (t < 64) {
        #pragma unroll
        for (int q = 0; q < KNN; ++q) { skd[t][q] = finf(); ski[t][q] = 0; }
    }
    float thr = finf();
    int   maxpos = 0;
    int   grow = row0 + t;   // valid when t < 64
    __syncthreads();

    for (int ct = 0; ct < NPTS / 64; ++ct) {
        int col0 = ct * 64;
        // load col tile transposed
        for (int e = t; e < 64 * CDIM; e += 128) {
            int c = e >> 6, k = e & 63;
            Xc[k][c] = x[(col0 + c) * CDIM + k];
        }
        if (t < 64) sqc[t] = g_sq[col0 + t];
        __syncthreads();

        // 8x4 register microtile dot products
        float acc[8][4];
        #pragma unroll
        for (int i = 0; i < 8; ++i)
            #pragma unroll
            for (int j = 0; j < 4; ++j) acc[i][j] = 0.f;

        #pragma unroll 8
        for (int k = 0; k < CDIM; ++k) {
            float bv[4], av[8];
            #pragma unroll
            for (int j = 0; j < 4; ++j) bv[j] = Xc[k][tx * 4 + j];
            #pragma unroll
            for (int i = 0; i < 8; ++i) av[i] = Xr[k][ty * 8 + i];
            #pragma unroll
            for (int i = 0; i < 8; ++i)
                #pragma unroll
                for (int j = 0; j < 4; ++j) acc[i][j] += av[i] * bv[j];
        }
        __syncthreads();   // all reads of Xc done

        // write d' tile into the Xc buffer: dtile[r][c]
        #pragma unroll
        for (int i = 0; i < 8; ++i)
            #pragma unroll
            for (int j = 0; j < 4; ++j)
                Xc[ty * 8 + i][tx * 4 + j] = sqc[tx * 4 + j] - 2.0f * acc[i][j];
        __syncthreads();

        // streaming top-K update: thread t owns row t
        if (t < 64) {
            #pragma unroll 4
            for (int c = 0; c < 64; ++c) {
                float d = Xc[t][c];
                int gcol = col0 + c;
                if (d < thr && gcol != grow) {
                    skd[t][maxpos] = d;
                    ski[t][maxpos] = gcol;
                    float m = skd[t][0]; int mp = 0;
                    #pragma unroll
                    for (int q = 1; q < KNN; ++q) {
                        float v = skd[t][q];
                        if (v > m) { m = v; mp = q; }
                    }
                    thr = m; maxpos = mp;
                }
            }
        }
        __syncthreads();
    }

    if (t < 64) {
        #pragma unroll
        for (int q = 0; q < KNN; ++q)
            g_idx[grow * KNN + q] = ski[t][q];
    }
}

// ---------------------------------------------------------------------------
// Kernel 4: out[i,o] = relu(A[i,o] + max_j B[idx[i,j], o]) with the
// (N,C,R)->(N,R,C) transpose fused into a coalesced smem-staged write.
// Block: 256 threads, 4 source rows per block.
// ---------------------------------------------------------------------------
__global__ void out_kernel(float* __restrict__ y) {
    __shared__ int   nbr[4][KNN];
    __shared__ float sm[4][OUTC];
    int t  = threadIdx.x;
    int i0 = blockIdx.x * 4;

    if (t < 4 * KNN) nbr[t >> 4][t & 15] = g_idx[i0 * KNN + t];
    __syncthreads();

    #pragma unroll
    for (int il = 0; il < 4; ++il) {
        int i = i0 + il;
        float m = -finf();
        #pragma unroll
        for (int j = 0; j < KNN; ++j)
            m = fmaxf(m, g_B[nbr[il][j] * OUTC + t]);
        float v = g_A[i * OUTC + t] + m;
        sm[il][t] = fmaxf(v, 0.f);
    }
    __syncthreads();

    // y[(i*4 + rr)*64 + c] = out[i, c*4 + rr]; fully coalesced writes
    for (int e = t; e < 4 * OUTC; e += 256) {
        int il = e >> 8;
        int rr = (e >> 6) & 3;
        int c  = e & 63;
        y[i0 * OUTC + e] = sm[il][c * 4 + rr];
    }
}

// ---------------------------------------------------------------------------
extern "C" void kernel_launch(void* const* d_in, const int* in_sizes, int n_in,
                              void* d_out, int out_size) {
    const float* x = (const float*)d_in[0];
    const float* W = (const float*)d_in[1];
    const float* b = (const float*)d_in[2];
    float* y = (float*)d_out;

    sq_kernel<<<NPTS * 32 / 256, 256>>>(x);
    gemmAB_kernel<<<NPTS / 8, 256>>>(x, W, b);
    knn_kernel<<<NPTS / 64, 128>>>(x);
    out_kernel<<<NPTS / 4, 256>>>(y);
}

// round 3
// speedup vs baseline: 2.3350x; 2.3350x over previous
#include <cuda_runtime.h>
#include <cuda_bf16.h>
#include <cstdint>

#define NPTS 16384
#define CDIM 64
#define KNN  16
#define KL   20      // approx top-K per column-half
#define KTOT 40      // union size passed to exact rerank
#define OUTC 256     // C*R
#define MROWS 64     // rows per knn CTA
#define NTILE 128    // cols per knn tile

__device__ float g_sq[NPTS];
__device__ __nv_bfloat16 g_xbf[NPTS * CDIM];
__device__ int   g_idx40[NPTS * KTOT];
__device__ int   g_idx[NPTS * KNN];
__device__ float g_A[NPTS * OUTC];
__device__ float g_B[NPTS * OUTC];

__device__ __forceinline__ float finf() { return __int_as_float(0x7f800000); }

__device__ __forceinline__ uint32_t smem_to_u32(const void* p) {
    uint32_t a;
    asm("{ .reg .u64 t; cvta.to.shared.u64 t, %1; cvt.u32.u64 %0, t; }" : "=r"(a) : "l"(p));
    return a;
}
__device__ __forceinline__ void ldsm_x4(uint32_t& r0, uint32_t& r1, uint32_t& r2,
                                        uint32_t& r3, uint32_t addr) {
    asm volatile("ldmatrix.sync.aligned.m8n8.x4.shared.b16 {%0,%1,%2,%3}, [%4];"
                 : "=r"(r0), "=r"(r1), "=r"(r2), "=r"(r3) : "r"(addr));
}
__device__ __forceinline__ void mma16816(float* d, const uint32_t* a,
                                         uint32_t b0, uint32_t b1) {
    asm volatile("mma.sync.aligned.m16n8k16.row.col.f32.bf16.bf16.f32 "
                 "{%0,%1,%2,%3}, {%4,%5,%6,%7}, {%8,%9}, {%0,%1,%2,%3};"
                 : "+f"(d[0]), "+f"(d[1]), "+f"(d[2]), "+f"(d[3])
                 : "r"(a[0]), "r"(a[1]), "r"(a[2]), "r"(a[3]), "r"(b0), "r"(b1));
}

// ---------------------------------------------------------------------------
// Kernel 1: squared norms (fp32) + bf16 copy of x
// ---------------------------------------------------------------------------
__global__ void prep_kernel(const float* __restrict__ x) {
    int w    = (blockIdx.x * blockDim.x + threadIdx.x) >> 5;
    int lane = threadIdx.x & 31;
    float v0 = x[w * CDIM + lane];
    float v1 = x[w * CDIM + 32 + lane];
    g_xbf[w * CDIM + lane]      = __float2bfloat16(v0);
    g_xbf[w * CDIM + 32 + lane] = __float2bfloat16(v1);
    float s = v0 * v0 + v1 * v1;
    #pragma unroll
    for (int o = 16; o; o >>= 1) s += __shfl_xor_sync(0xffffffffu, s, o);
    if (lane == 0) g_sq[w] = s;
}

// ---------------------------------------------------------------------------
// Kernel 2: A = x @ (W1 - W2) + b ; B = x @ W2   (exact fp32)
// ---------------------------------------------------------------------------
__global__ void gemmAB_kernel(const float* __restrict__ x,
                              const float* __restrict__ W,
                              const float* __restrict__ b) {
    __shared__ float xs[8][CDIM];
    int row0 = blockIdx.x * 8;
    int t = threadIdx.x;
    for (int e = t; e < 8 * CDIM; e += 256)
        xs[e >> 6][e & 63] = x[row0 * CDIM + e];
    __syncthreads();
    float accA[8], accB[8];
    #pragma unroll
    for (int r = 0; r < 8; ++r) { accA[r] = 0.f; accB[r] = 0.f; }
    #pragma unroll 4
    for (int c = 0; c < CDIM; ++c) {
        float w1 = W[c * OUTC + t];
        float w2 = W[(c + CDIM) * OUTC + t];
        float wd = w1 - w2;
        #pragma unroll
        for (int r = 0; r < 8; ++r) {
            float xv = xs[r][c];
            accA[r] += xv * wd;
            accB[r] += xv * w2;
        }
    }
    float bias = b[t];
    #pragma unroll
    for (int r = 0; r < 8; ++r) {
        g_A[(row0 + r) * OUTC + t] = accA[r] + bias;
        g_B[(row0 + r) * OUTC + t] = accB[r];
    }
}

// ---------------------------------------------------------------------------
// Kernel 3: bf16 mma.sync gram matrix + streaming approx top-20 per col-half.
// CTA = 64 rows, tile = 64x128. 8 warps: wr in {0,1} (32 rows), wc in {0..3}
// (32 cols). A-frags register-resident for the whole sweep.
// ---------------------------------------------------------------------------
#define XSTRIDE 144          // bytes per smem row (72 bf16): conflict-free ldmatrix
#define SSTRIDE 134          // floats per S row
#define OFF_SQC 0
#define OFF_XR  512
#define OFF_XC  (OFF_XR + MROWS * XSTRIDE)              // 512 + 9216 = 9728
#define OFF_S   (OFF_XC + NTILE * XSTRIDE)              // 28160
#define OFF_SKD (OFF_S + MROWS * SSTRIDE * 4)           // 62464
#define OFF_SKI (OFF_SKD + 2 * MROWS * KL * 4)          // 72704
#define KNN_SMEM (OFF_SKI + 2 * MROWS * KL * 4)         // 82944

__global__ void __launch_bounds__(256) knn_tc_kernel() {
    extern __shared__ char sm[];
    float* sqc = (float*)(sm + OFF_SQC);
    char*  Xr  = sm + OFF_XR;
    char*  Xc  = sm + OFF_XC;
    float* S   = (float*)(sm + OFF_S);
    float* skd = (float*)(sm + OFF_SKD);
    int*   ski = (int*)(sm + OFF_SKI);
    uint32_t XrB = smem_to_u32(Xr);
    uint32_t XcB = smem_to_u32(Xc);

    int t    = threadIdx.x;
    int lane = t & 31;
    int wid  = t >> 5;
    int wr   = wid >> 2;          // 0..1
    int wc   = wid & 3;           // 0..3
    int m0   = wr * 32;
    int n0   = wc * 32;
    int row0 = blockIdx.x * MROWS;

    int quad = lane >> 3;
    int idr  = lane & 7;
    int rsel = (quad & 1) * 8 + idr;      // row within 16-row group
    int csel = (quad >> 1) * 8;           // elem col offset (0 or 8)

    const uint4* xbf4 = (const uint4*)g_xbf;   // 8 chunks of 16B per row

    // load Xr (64 rows x 64 bf16)
    for (int e = t; e < MROWS * 8; e += 256) {
        int r = e >> 3, ch = e & 7;
        *(uint4*)(Xr + r * XSTRIDE + ch * 16) = xbf4[(row0 + r) * 8 + ch];
    }
    // init top-K lists: thread t<128 owns (row t>>1, half t&1)
    if (t < 128) {
        #pragma unroll
        for (int q = 0; q < KL; ++q) { skd[t * KL + q] = finf(); ski[t * KL + q] = 0; }
    }
    __syncthreads();

    // preload A fragments: 2 m-tiles x 4 k-steps x 4 regs
    uint32_t afr[2][4][4];
    #pragma unroll
    for (int mi = 0; mi < 2; ++mi)
        #pragma unroll
        for (int ks = 0; ks < 4; ++ks) {
            uint32_t addr = XrB + (m0 + 16 * mi + rsel) * XSTRIDE + (ks * 16 + csel) * 2;
            ldsm_x4(afr[mi][ks][0], afr[mi][ks][1], afr[mi][ks][2], afr[mi][ks][3], addr);
        }

    float thr = finf();
    int   maxpos = 0;
    int   myrow  = t >> 1;            // valid for t<128
    int   grow   = row0 + myrow;

    for (int ct = 0; ct < NPTS / NTILE; ++ct) {
        int col0 = ct * NTILE;
        // load Xc (128 rows x 64 bf16) + sqc
        for (int e = t; e < NTILE * 8; e += 256) {
            int r = e >> 3, ch = e & 7;
            *(uint4*)(Xc + r * XSTRIDE + ch * 16) = xbf4[(col0 + r) * 8 + ch];
        }
        if (t < 128) sqc[t] = g_sq[col0 + t];
        __syncthreads();

        float acc[2][4][4];
        #pragma unroll
        for (int mi = 0; mi < 2; ++mi)
            #pragma unroll
            for (int nt = 0; nt < 4; ++nt)
                #pragma unroll
                for (int q = 0; q < 4; ++q) acc[mi][nt][q] = 0.f;

        #pragma unroll
        for (int ks = 0; ks < 4; ++ks) {
            uint32_t bfr[4][2];
            #pragma unroll
            for (int g = 0; g < 2; ++g) {
                uint32_t r0, r1, r2, r3;
                uint32_t addr = XcB + (n0 + 16 * g + rsel) * XSTRIDE + (ks * 16 + csel) * 2;
                ldsm_x4(r0, r1, r2, r3, addr);
                bfr[g * 2][0]     = r0; bfr[g * 2][1]     = r2;
                bfr[g * 2 + 1][0] = r1; bfr[g * 2 + 1][1] = r3;
            }
            #pragma unroll
            for (int mi = 0; mi < 2; ++mi)
                #pragma unroll
                for (int nt = 0; nt < 4; ++nt)
                    mma16816(acc[mi][nt], afr[mi][ks], bfr[nt][0], bfr[nt][1]);
        }

        // epilogue: d' = sqc[c] - 2*dot -> S
        #pragma unroll
        for (int nt = 0; nt < 4; ++nt) {
            int c0 = n0 + nt * 8 + (lane & 3) * 2;
            float2 sq2 = *(float2*)&sqc[c0];
            #pragma unroll
            for (int mi = 0; mi < 2; ++mi) {
                int ra = m0 + 16 * mi + (lane >> 2);
                float2 v0, v1;
                v0.x = fmaf(-2.f, acc[mi][nt][0], sq2.x);
                v0.y = fmaf(-2.f, acc[mi][nt][1], sq2.y);
                v1.x = fmaf(-2.f, acc[mi][nt][2], sq2.x);
                v1.y = fmaf(-2.f, acc[mi][nt][3], sq2.y);
                *(float2*)&S[ra * SSTRIDE + c0]       = v0;
                *(float2*)&S[(ra + 8) * SSTRIDE + c0] = v1;
            }
        }
        __syncthreads();

        // streaming top-KL: thread t<128 scans row (t>>1), cols (t&1)+2i
        if (t < 128) {
            int hoff = t & 1;
            #pragma unroll 4
            for (int i = 0; i < 64; ++i) {
                int c = hoff + 2 * i;
                float d = S[myrow * SSTRIDE + c];
                int gcol = col0 + c;
                if (d < thr && gcol != grow) {
                    skd[t * KL + maxpos] = d;
                    ski[t * KL + maxpos] = gcol;
                    float m = skd[t * KL]; int mp = 0;
                    #pragma unroll
                    for (int q = 1; q < KL; ++q) {
                        float v = skd[t * KL + q];
                        if (v > m) { m = v; mp = q; }
                    }
                    thr = m; maxpos = mp;
                }
            }
        }
        __syncthreads();
    }

    if (t < 128) {
        #pragma unroll
        for (int q = 0; q < KL; ++q)
            g_idx40[grow * KTOT + (t & 1) * KL + q] = ski[t * KL + q];
    }
}

// ---------------------------------------------------------------------------
// Kernel 4: exact fp32 rerank of 40 candidates -> true top-16. 1 warp / row.
// ---------------------------------------------------------------------------
__global__ void rerank_kernel(const float* __restrict__ x) {
    __shared__ float xr[8][CDIM];
    __shared__ int   sc[8][KTOT];
    __shared__ float sd[8][KTOT];
    int w = threadIdx.x >> 5, lane = threadIdx.x & 31;
    int row = blockIdx.x * 8 + w;

    xr[w][lane]      = x[row * CDIM + lane];
    xr[w][32 + lane] = x[row * CDIM + 32 + lane];
    sc[w][lane] = g_idx40[row * KTOT + lane];
    if (lane < 8) sc[w][32 + lane] = g_idx40[row * KTOT + 32 + lane];
    __syncwarp();

    #pragma unroll 4
    for (int c = 0; c < KTOT; ++c) {
        int cand = sc[w][c];
        float v = x[cand * CDIM + lane] * xr[w][lane]
                + x[cand * CDIM + 32 + lane] * xr[w][32 + lane];
        #pragma unroll
        for (int o = 16; o; o >>= 1) v += __shfl_xor_sync(0xffffffffu, v, o);
        if (lane == 0) sd[w][c] = fmaf(-2.0f, v, g_sq[cand]);
    }
    __syncwarp();

    float va = sd[w][lane];
    float vb = (lane < 8) ? sd[w][32 + lane] : finf();
    #pragma unroll
    for (int it = 0; it < KNN; ++it) {
        float bv = va; int bs = lane;
        if (vb < bv) { bv = vb; bs = lane + 32; }
        #pragma unroll
        for (int o = 16; o; o >>= 1) {
            float ov = __shfl_xor_sync(0xffffffffu, bv, o);
            int   os = __shfl_xor_sync(0xffffffffu, bs, o);
            if (ov < bv || (ov == bv && os < bs)) { bv = ov; bs = os; }
        }
        if (lane == 0) g_idx[row * KNN + it] = sc[w][bs];
        if (bs < 32) { if (lane == bs) va = finf(); }
        else if (lane == bs - 32) vb = finf();
    }
}

// ---------------------------------------------------------------------------
// Kernel 5: out = relu(A[i] + max_j B[idx[i,j]]) + fused transpose
// ---------------------------------------------------------------------------
__global__ void out_kernel(float* __restrict__ y) {
    __shared__ int   nbr[4][KNN];
    __shared__ float smv[4][OUTC];
    int t  = threadIdx.x;
    int i0 = blockIdx.x * 4;

    if (t < 4 * KNN) nbr[t >> 4][t & 15] = g_idx[i0 * KNN + t];
    __syncthreads();

    #pragma unroll
    for (int il = 0; il < 4; ++il) {
        int i = i0 + il;
        float m = -finf();
        #pragma unroll
        for (int j = 0; j < KNN; ++j)
            m = fmaxf(m, g_B[nbr[il][j] * OUTC + t]);
        float v = g_A[i * OUTC + t] + m;
        smv[il][t] = fmaxf(v, 0.f);
    }
    __syncthreads();

    for (int e = t; e < 4 * OUTC; e += 256) {
        int c = e & 63;
        int rr = (e >> 6) & 3;
        int il = e >> 8;
        y[i0 * OUTC + e] = smv[il][c * 4 + rr];
    }
}

// ---------------------------------------------------------------------------
extern "C" void kernel_launch(void* const* d_in, const int* in_sizes, int n_in,
                              void* d_out, int out_size) {
    const float* x = (const float*)d_in[0];
    const float* W = (const float*)d_in[1];
    const float* b = (const float*)d_in[2];
    float* y = (float*)d_out;

    static bool attr_done = false;
    if (!attr_done) {
        cudaFuncSetAttribute(knn_tc_kernel,
                             cudaFuncAttributeMaxDynamicSharedMemorySize, KNN_SMEM);
        attr_done = true;
    }

    prep_kernel<<<NPTS * 32 / 256, 256>>>(x);
    gemmAB_kernel<<<NPTS / 8, 256>>>(x, W, b);
    knn_tc_kernel<<<NPTS / MROWS, 256, KNN_SMEM>>>();
    rerank_kernel<<<NPTS / 8, 256>>>(x);
    out_kernel<<<NPTS / 4, 256>>>(y);
}

// round 4
// speedup vs baseline: 3.8545x; 1.6508x over previous
#include <cuda_runtime.h>
#include <cuda_bf16.h>
#include <cstdint>

#define NPTS 16384
#define CDIM 64
#define KNN  16
#define K2   20      // approx top-K per row (single list)
#define K2P  21      // padded stride (gcd(21,32)=1 -> conflict-free)
#define CAP  48      // candidate buffer capacity per row per tile
#define OUTC 256     // C*R
#define MROWS 64     // rows per knn CTA
#define NTILE 128    // cols per knn tile

__device__ float g_sq[NPTS];
__device__ __nv_bfloat16 g_xbf[NPTS * CDIM];
__device__ int   g_idx20[NPTS * K2];
__device__ int   g_idx[NPTS * KNN];
__device__ float g_A[NPTS * OUTC];
__device__ float g_B[NPTS * OUTC];

__device__ __forceinline__ float finf() { return __int_as_float(0x7f800000); }

__device__ __forceinline__ uint32_t smem_to_u32(const void* p) {
    uint32_t a;
    asm("{ .reg .u64 t; cvta.to.shared.u64 t, %1; cvt.u32.u64 %0, t; }" : "=r"(a) : "l"(p));
    return a;
}
__device__ __forceinline__ void ldsm_x4(uint32_t& r0, uint32_t& r1, uint32_t& r2,
                                        uint32_t& r3, uint32_t addr) {
    asm volatile("ldmatrix.sync.aligned.m8n8.x4.shared.b16 {%0,%1,%2,%3}, [%4];"
                 : "=r"(r0), "=r"(r1), "=r"(r2), "=r"(r3) : "r"(addr));
}
__device__ __forceinline__ void mma16816(float* d, const uint32_t* a,
                                         uint32_t b0, uint32_t b1) {
    asm volatile("mma.sync.aligned.m16n8k16.row.col.f32.bf16.bf16.f32 "
                 "{%0,%1,%2,%3}, {%4,%5,%6,%7}, {%8,%9}, {%0,%1,%2,%3};"
                 : "+f"(d[0]), "+f"(d[1]), "+f"(d[2]), "+f"(d[3])
                 : "r"(a[0]), "r"(a[1]), "r"(a[2]), "r"(a[3]), "r"(b0), "r"(b1));
}

// ---------------------------------------------------------------------------
// Kernel 1: squared norms (fp32) + bf16 copy of x
// ---------------------------------------------------------------------------
__global__ void prep_kernel(const float* __restrict__ x) {
    int w    = (blockIdx.x * blockDim.x + threadIdx.x) >> 5;
    int lane = threadIdx.x & 31;
    float v0 = x[w * CDIM + lane];
    float v1 = x[w * CDIM + 32 + lane];
    g_xbf[w * CDIM + lane]      = __float2bfloat16(v0);
    g_xbf[w * CDIM + 32 + lane] = __float2bfloat16(v1);
    float s = v0 * v0 + v1 * v1;
    #pragma unroll
    for (int o = 16; o; o >>= 1) s += __shfl_xor_sync(0xffffffffu, s, o);
    if (lane == 0) g_sq[w] = s;
}

// ---------------------------------------------------------------------------
// Kernel 2: A = x @ (W1 - W2) + b ; B = x @ W2   (exact fp32)
// ---------------------------------------------------------------------------
__global__ void gemmAB_kernel(const float* __restrict__ x,
                              const float* __restrict__ W,
                              const float* __restrict__ b) {
    __shared__ float xs[8][CDIM];
    int row0 = blockIdx.x * 8;
    int t = threadIdx.x;
    for (int e = t; e < 8 * CDIM; e += 256)
        xs[e >> 6][e & 63] = x[row0 * CDIM + e];
    __syncthreads();
    float accA[8], accB[8];
    #pragma unroll
    for (int r = 0; r < 8; ++r) { accA[r] = 0.f; accB[r] = 0.f; }
    #pragma unroll 4
    for (int c = 0; c < CDIM; ++c) {
        float w1 = W[c * OUTC + t];
        float w2 = W[(c + CDIM) * OUTC + t];
        float wd = w1 - w2;
        #pragma unroll
        for (int r = 0; r < 8; ++r) {
            float xv = xs[r][c];
            accA[r] += xv * wd;
            accB[r] += xv * w2;
        }
    }
    float bias = b[t];
    #pragma unroll
    for (int r = 0; r < 8; ++r) {
        g_A[(row0 + r) * OUTC + t] = accA[r] + bias;
        g_B[(row0 + r) * OUTC + t] = accB[r];
    }
}

// ---------------------------------------------------------------------------
// Kernel 3: bf16 mma.sync gram + threshold-filtered streaming top-20.
// CTA = 64 rows; per 128-col tile: MMA in regs, filter vs per-row threshold,
// rare pushes to per-row buffers, owner threads drain. Seed tile (diagonal)
// and overflow tiles use a full S-tile scan fallback.
// ---------------------------------------------------------------------------
#define XSTRIDE 144          // bytes per smem row (conflict-free ldmatrix)
#define SSTRIDE 134          // floats per S row (2-way max on scans)
#define OFF_SQC 0
#define OFF_THR 512
#define OFF_CNT 768
#define OFF_OVF 1024
#define OFF_XR  1040
#define OFF_XC  (OFF_XR + MROWS * XSTRIDE)            // 10256
#define OFF_S   (OFF_XC + NTILE * XSTRIDE)            // 28688
#define OFF_SKD (OFF_S + MROWS * SSTRIDE * 4)         // 62992
#define OFF_SKI (OFF_SKD + MROWS * K2P * 4)           // 68368
#define OFF_BUFD (OFF_SKI + MROWS * K2P * 4)          // 73744
#define OFF_BUFC (OFF_BUFD + MROWS * CAP * 4)         // 86032
#define KNN_SMEM (OFF_BUFC + MROWS * CAP * 4)         // 98320

__global__ void __launch_bounds__(256, 2) knn_tc_kernel() {
    extern __shared__ char sm[];
    float* sqc  = (float*)(sm + OFF_SQC);
    float* thrS = (float*)(sm + OFF_THR);
    int*   cnt  = (int*)(sm + OFF_CNT);
    int*   ovf  = (int*)(sm + OFF_OVF);
    char*  Xr   = sm + OFF_XR;
    char*  Xc   = sm + OFF_XC;
    float* S    = (float*)(sm + OFF_S);
    float* skd  = (float*)(sm + OFF_SKD);
    int*   ski  = (int*)(sm + OFF_SKI);
    float* bufd = (float*)(sm + OFF_BUFD);
    int*   bufc = (int*)(sm + OFF_BUFC);
    uint32_t XrB = smem_to_u32(Xr);
    uint32_t XcB = smem_to_u32(Xc);

    int t    = threadIdx.x;
    int lane = t & 31;
    int wid  = t >> 5;
    int m0   = (wid >> 2) * 32;
    int n0   = (wid & 3) * 32;
    int row0 = blockIdx.x * MROWS;

    int quad = lane >> 3;
    int rsel = (quad & 1) * 8 + (lane & 7);
    int csel = (quad >> 1) * 8;

    const uint4* xbf4 = (const uint4*)g_xbf;

    for (int e = t; e < MROWS * 8; e += 256) {
        int r = e >> 3, ch = e & 7;
        *(uint4*)(Xr + r * XSTRIDE + ch * 16) = xbf4[(row0 + r) * 8 + ch];
    }
    if (t < MROWS) {
        #pragma unroll
        for (int q = 0; q < K2; ++q) { skd[t * K2P + q] = finf(); ski[t * K2P + q] = 0; }
        cnt[t] = 0;
        thrS[t] = finf();
    }
    if (t == 0) ovf[0] = 0;
    __syncthreads();

    // A fragments register-resident for the whole sweep
    uint32_t afr[2][4][4];
    #pragma unroll
    for (int mi = 0; mi < 2; ++mi)
        #pragma unroll
        for (int ks = 0; ks < 4; ++ks) {
            uint32_t addr = XrB + (m0 + 16 * mi + rsel) * XSTRIDE + (ks * 16 + csel) * 2;
            ldsm_x4(afr[mi][ks][0], afr[mi][ks][1], afr[mi][ks][2], afr[mi][ks][3], addr);
        }

    float thr = finf();      // owner-thread (t<64) running 20th-smallest
    int   maxpos = 0;
    int   growT = row0 + t;  // owner's global row

    int dt = (int)(blockIdx.x >> 1);   // diagonal tile index

    for (int step = 0; step < NPTS / NTILE; ++step) {
        int ct = (step == 0) ? dt : ((step - 1 < dt) ? step - 1 : step);
        bool force = (step == 0);
        int col0 = ct * NTILE;

        for (int e = t; e < NTILE * 8; e += 256) {
            int r = e >> 3, ch = e & 7;
            *(uint4*)(Xc + r * XSTRIDE + ch * 16) = xbf4[(col0 + r) * 8 + ch];
        }
        if (t < NTILE) sqc[t] = g_sq[col0 + t];
        __syncthreads();

        float acc[2][4][4];
        #pragma unroll
        for (int mi = 0; mi < 2; ++mi)
            #pragma unroll
            for (int nt = 0; nt < 4; ++nt)
                #pragma unroll
                for (int q = 0; q < 4; ++q) acc[mi][nt][q] = 0.f;

        #pragma unroll
        for (int ks = 0; ks < 4; ++ks) {
            uint32_t bfr[4][2];
            #pragma unroll
            for (int g = 0; g < 2; ++g) {
                uint32_t r0, r1, r2, r3;
                uint32_t addr = XcB + (n0 + 16 * g + rsel) * XSTRIDE + (ks * 16 + csel) * 2;
                ldsm_x4(r0, r1, r2, r3, addr);
                bfr[g * 2][0]     = r0; bfr[g * 2][1]     = r2;
                bfr[g * 2 + 1][0] = r1; bfr[g * 2 + 1][1] = r3;
            }
            #pragma unroll
            for (int mi = 0; mi < 2; ++mi)
                #pragma unroll
                for (int nt = 0; nt < 4; ++nt)
                    mma16816(acc[mi][nt], afr[mi][ks], bfr[nt][0], bfr[nt][1]);
        }

        // ---- filter + push (skipped on seed tile) ----
        if (!force) {
            #pragma unroll
            for (int mi = 0; mi < 2; ++mi)
                #pragma unroll
                for (int half = 0; half < 2; ++half) {
                    int r = m0 + 16 * mi + (lane >> 2) + 8 * half;
                    float tr = thrS[r];
                    int growr = row0 + r;
                    #pragma unroll
                    for (int nt = 0; nt < 4; ++nt) {
                        int c0 = n0 + nt * 8 + (lane & 3) * 2;
                        float d0 = fmaf(-2.f, acc[mi][nt][half * 2],     sqc[c0]);
                        float d1 = fmaf(-2.f, acc[mi][nt][half * 2 + 1], sqc[c0 + 1]);
                        int g0 = col0 + c0;
                        if (d0 < tr && g0 != growr) {
                            int i = atomicAdd(&cnt[r], 1);
                            if (i < CAP) { bufd[r * CAP + i] = d0; bufc[r * CAP + i] = g0; }
                            else ovf[0] = 1;
                        }
                        if (d1 < tr && g0 + 1 != growr) {
                            int i = atomicAdd(&cnt[r], 1);
                            if (i < CAP) { bufd[r * CAP + i] = d1; bufc[r * CAP + i] = g0 + 1; }
                            else ovf[0] = 1;
                        }
                    }
                }
        }
        __syncthreads();

        bool dofb = force || (ovf[0] != 0);
        if (!dofb) {
            if (t < MROWS) {
                int n = cnt[t]; if (n > CAP) n = CAP;
                for (int i = 0; i < n; ++i) {
                    float d = bufd[t * CAP + i];
                    if (d < thr) {
                        skd[t * K2P + maxpos] = d;
                        ski[t * K2P + maxpos] = bufc[t * CAP + i];
                        float m = skd[t * K2P]; int mp = 0;
                        #pragma unroll
                        for (int q = 1; q < K2; ++q) {
                            float v = skd[t * K2P + q];
                            if (v > m) { m = v; mp = q; }
                        }
                        thr = m; maxpos = mp;
                    }
                }
            }
        } else {
            // fallback: write full S tile from live acc, then owners scan
            #pragma unroll
            for (int nt = 0; nt < 4; ++nt) {
                int c0 = n0 + nt * 8 + (lane & 3) * 2;
                float2 sq2 = *(float2*)&sqc[c0];
                #pragma unroll
                for (int mi = 0; mi < 2; ++mi) {
                    int ra = m0 + 16 * mi + (lane >> 2);
                    float2 v0, v1;
                    v0.x = fmaf(-2.f, acc[mi][nt][0], sq2.x);
                    v0.y = fmaf(-2.f, acc[mi][nt][1], sq2.y);
                    v1.x = fmaf(-2.f, acc[mi][nt][2], sq2.x);
                    v1.y = fmaf(-2.f, acc[mi][nt][3], sq2.y);
                    *(float2*)&S[ra * SSTRIDE + c0]       = v0;
                    *(float2*)&S[(ra + 8) * SSTRIDE + c0] = v1;
                }
            }
            __syncthreads();
            if (t < MROWS) {
                #pragma unroll 4
                for (int c = 0; c < NTILE; ++c) {
                    float d = S[t * SSTRIDE + c];
                    int g = col0 + c;
                    if (d < thr && g != growT) {
                        skd[t * K2P + maxpos] = d;
                        ski[t * K2P + maxpos] = g;
                        float m = skd[t * K2P]; int mp = 0;
                        #pragma unroll
                        for (int q = 1; q < K2; ++q) {
                            float v = skd[t * K2P + q];
                            if (v > m) { m = v; mp = q; }
                        }
                        thr = m; maxpos = mp;
                    }
                }
            }
        }
        if (t < MROWS) { cnt[t] = 0; thrS[t] = thr; }
        if (t == 0) ovf[0] = 0;
        __syncthreads();
    }

    if (t < MROWS) {
        #pragma unroll
        for (int q = 0; q < K2; ++q)
            g_idx20[growT * K2 + q] = ski[t * K2P + q];
    }
}

// ---------------------------------------------------------------------------
// Kernel 4: exact fp32 rerank of 20 candidates -> true top-16. 1 warp / row.
// ---------------------------------------------------------------------------
__global__ void rerank_kernel(const float* __restrict__ x) {
    __shared__ float xr[8][CDIM];
    __shared__ int   sc[8][K2];
    __shared__ float sd[8][K2];
    int w = threadIdx.x >> 5, lane = threadIdx.x & 31;
    int row = blockIdx.x * 8 + w;

    xr[w][lane]      = x[row * CDIM + lane];
    xr[w][32 + lane] = x[row * CDIM + 32 + lane];
    if (lane < K2) sc[w][lane] = g_idx20[row * K2 + lane];
    __syncwarp();

    #pragma unroll 4
    for (int c = 0; c < K2; ++c) {
        int cand = sc[w][c];
        float v = x[cand * CDIM + lane] * xr[w][lane]
                + x[cand * CDIM + 32 + lane] * xr[w][32 + lane];
        #pragma unroll
        for (int o = 16; o; o >>= 1) v += __shfl_xor_sync(0xffffffffu, v, o);
        if (lane == 0) sd[w][c] = fmaf(-2.0f, v, g_sq[cand]);
    }
    __syncwarp();

    float d = (lane < K2) ? sd[w][lane] : finf();
    int cand = (lane < K2) ? sc[w][lane] : -1;
    unsigned act = 0xFFFFFu;   // lanes 0..19 active
    #pragma unroll
    for (int rep = 0; rep < K2 - KNN; ++rep) {
        float dm = ((act >> lane) & 1) ? d : -finf();
        float m = dm; int am = lane;
        #pragma unroll
        for (int o = 16; o; o >>= 1) {
            float om = __shfl_xor_sync(0xffffffffu, m, o);
            int   oa = __shfl_xor_sync(0xffffffffu, am, o);
            if (om > m || (om == m && oa < am)) { m = om; am = oa; }
        }
        act &= ~(1u << am);   // drop the largest distance
    }
    if ((act >> lane) & 1) {
        int pos = __popc(act & ((1u << lane) - 1u));
        g_idx[row * KNN + pos] = cand;
    }
}

// ---------------------------------------------------------------------------
// Kernel 5: out = relu(A[i] + max_j B[idx[i,j]]) + fused transpose
// ---------------------------------------------------------------------------
__global__ void out_kernel(float* __restrict__ y) {
    __shared__ int   nbr[4][KNN];
    __shared__ float smv[4][OUTC];
    int t  = threadIdx.x;
    int i0 = blockIdx.x * 4;

    if (t < 4 * KNN) nbr[t >> 4][t & 15] = g_idx[i0 * KNN + t];
    __syncthreads();

    #pragma unroll
    for (int il = 0; il < 4; ++il) {
        int i = i0 + il;
        float m = -finf();
        #pragma unroll
        for (int j = 0; j < KNN; ++j)
            m = fmaxf(m, g_B[nbr[il][j] * OUTC + t]);
        float v = g_A[i * OUTC + t] + m;
        smv[il][t] = fmaxf(v, 0.f);
    }
    __syncthreads();

    for (int e = t; e < 4 * OUTC; e += 256) {
        int c = e & 63;
        int rr = (e >> 6) & 3;
        int il = e >> 8;
        y[i0 * OUTC + e] = smv[il][c * 4 + rr];
    }
}

// ---------------------------------------------------------------------------
extern "C" void kernel_launch(void* const* d_in, const int* in_sizes, int n_in,
                              void* d_out, int out_size) {
    const float* x = (const float*)d_in[0];
    const float* W = (const float*)d_in[1];
    const float* b = (const float*)d_in[2];
    float* y = (float*)d_out;

    static bool attr_done = false;
    if (!attr_done) {
        cudaFuncSetAttribute(knn_tc_kernel,
                             cudaFuncAttributeMaxDynamicSharedMemorySize, KNN_SMEM);
        attr_done = true;
    }

    prep_kernel<<<NPTS * 32 / 256, 256>>>(x);
    gemmAB_kernel<<<NPTS / 8, 256>>>(x, W, b);
    knn_tc_kernel<<<NPTS / MROWS, 256, KNN_SMEM>>>();
    rerank_kernel<<<NPTS / 8, 256>>>(x);
    out_kernel<<<NPTS / 4, 256>>>(y);
}

// round 5
// speedup vs baseline: 4.7406x; 1.2299x over previous
#include <cuda_runtime.h>
#include <cuda_bf16.h>
#include <cstdint>

#define NPTS 16384
#define CDIM 64
#define KNN  16
#define K2   20      // approx top-K per row
#define K2P  21      // padded stride
#define CAP  32      // dedicated buffer slots/row (ext +64 in S region -> 96)
#define CAPX 96
#define OUTC 256     // C*R
#define MROWS 64     // rows per knn CTA
#define NTILE 256    // cols per knn step (2 halves of 128)

__device__ float g_sq[NPTS];
__device__ __nv_bfloat16 g_xbf[NPTS * CDIM];
__device__ int   g_idx20[NPTS * K2];
__device__ int   g_idx[NPTS * KNN];
__device__ float g_A[NPTS * OUTC];
__device__ float g_B[NPTS * OUTC];

__device__ __forceinline__ float finf() { return __int_as_float(0x7f800000); }

__device__ __forceinline__ uint32_t smem_to_u32(const void* p) {
    uint32_t a;
    asm("{ .reg .u64 t; cvta.to.shared.u64 t, %1; cvt.u32.u64 %0, t; }" : "=r"(a) : "l"(p));
    return a;
}
__device__ __forceinline__ void ldsm_x4(uint32_t& r0, uint32_t& r1, uint32_t& r2,
                                        uint32_t& r3, uint32_t addr) {
    asm volatile("ldmatrix.sync.aligned.m8n8.x4.shared.b16 {%0,%1,%2,%3}, [%4];"
                 : "=r"(r0), "=r"(r1), "=r"(r2), "=r"(r3) : "r"(addr));
}
__device__ __forceinline__ void mma16816(float* d, const uint32_t* a,
                                         uint32_t b0, uint32_t b1) {
    asm volatile("mma.sync.aligned.m16n8k16.row.col.f32.bf16.bf16.f32 "
                 "{%0,%1,%2,%3}, {%4,%5,%6,%7}, {%8,%9}, {%0,%1,%2,%3};"
                 : "+f"(d[0]), "+f"(d[1]), "+f"(d[2]), "+f"(d[3])
                 : "r"(a[0]), "r"(a[1]), "r"(a[2]), "r"(a[3]), "r"(b0), "r"(b1));
}
__device__ __forceinline__ void cpasync16(uint32_t dst, const void* src) {
    asm volatile("cp.async.cg.shared.global [%0], [%1], 16;" :: "r"(dst), "l"(src));
}

// ---------------------------------------------------------------------------
// Kernel 1: squared norms + bf16 copy
// ---------------------------------------------------------------------------
__global__ void prep_kernel(const float* __restrict__ x) {
    int w    = (blockIdx.x * blockDim.x + threadIdx.x) >> 5;
    int lane = threadIdx.x & 31;
    float v0 = x[w * CDIM + lane];
    float v1 = x[w * CDIM + 32 + lane];
    g_xbf[w * CDIM + lane]      = __float2bfloat16(v0);
    g_xbf[w * CDIM + 32 + lane] = __float2bfloat16(v1);
    float s = v0 * v0 + v1 * v1;
    #pragma unroll
    for (int o = 16; o; o >>= 1) s += __shfl_xor_sync(0xffffffffu, s, o);
    if (lane == 0) g_sq[w] = s;
}

// ---------------------------------------------------------------------------
// Kernel 2: A = x @ (W1 - W2) + b ; B = x @ W2   (exact fp32)
// ---------------------------------------------------------------------------
__global__ void gemmAB_kernel(const float* __restrict__ x,
                              const float* __restrict__ W,
                              const float* __restrict__ b) {
    __shared__ float xs[8][CDIM];
    int row0 = blockIdx.x * 8;
    int t = threadIdx.x;
    for (int e = t; e < 8 * CDIM; e += 256)
        xs[e >> 6][e & 63] = x[row0 * CDIM + e];
    __syncthreads();
    float accA[8], accB[8];
    #pragma unroll
    for (int r = 0; r < 8; ++r) { accA[r] = 0.f; accB[r] = 0.f; }
    #pragma unroll 4
    for (int c = 0; c < CDIM; ++c) {
        float w1 = W[c * OUTC + t];
        float w2 = W[(c + CDIM) * OUTC + t];
        float wd = w1 - w2;
        #pragma unroll
        for (int r = 0; r < 8; ++r) {
            float xv = xs[r][c];
            accA[r] += xv * wd;
            accB[r] += xv * w2;
        }
    }
    float bias = b[t];
    #pragma unroll
    for (int r = 0; r < 8; ++r) {
        g_A[(row0 + r) * OUTC + t] = accA[r] + bias;
        g_B[(row0 + r) * OUTC + t] = accB[r];
    }
}

// ---------------------------------------------------------------------------
// Kernel 3: bf16 mma.sync gram + filtered top-20, 256-col steps.
// ---------------------------------------------------------------------------
#define XSTRIDE 144
#define SSTRIDE 134
#define OFF_SQC 0                                       // 256 floats
#define OFF_THR 1024                                    // 64 floats
#define OFF_CNT 1280                                    // 64 ints
#define OFF_XR  1552
#define OFF_XC  (OFF_XR + MROWS * XSTRIDE)              // 10768
#define OFF_S   (OFF_XC + NTILE * XSTRIDE)              // 47632
#define OFF_SKD (OFF_S + MROWS * SSTRIDE * 4)           // 81936
#define OFF_SKI (OFF_SKD + MROWS * K2P * 4)             // 87312
#define OFF_BUFD (OFF_SKI + MROWS * K2P * 4)            // 92688
#define OFF_BUFC (OFF_BUFD + MROWS * CAP * 4)           // 100880
#define KNN_SMEM (OFF_BUFC + MROWS * CAP * 4)           // 109072

__global__ void __launch_bounds__(256, 2) knn_tc_kernel() {
    extern __shared__ char sm[];
    float* sqc  = (float*)(sm + OFF_SQC);
    float* thrS = (float*)(sm + OFF_THR);
    int*   cnt  = (int*)(sm + OFF_CNT);
    char*  Xr   = sm + OFF_XR;
    char*  Xc   = sm + OFF_XC;
    float* S    = (float*)(sm + OFF_S);
    float* skd  = (float*)(sm + OFF_SKD);
    int*   ski  = (int*)(sm + OFF_SKI);
    float* bufd = (float*)(sm + OFF_BUFD);
    int*   bufc = (int*)(sm + OFF_BUFC);
    uint32_t XrB = smem_to_u32(Xr);
    uint32_t XcB = smem_to_u32(Xc);

    int t    = threadIdx.x;
    int lane = t & 31;
    int wid  = t >> 5;
    int m0   = (wid >> 2) * 32;
    int n0   = (wid & 3) * 32;       // within a 128-col half
    int row0 = blockIdx.x * MROWS;

    int quad = lane >> 3;
    int rsel = (quad & 1) * 8 + (lane & 7);
    int csel = (quad >> 1) * 8;

    const uint4* xbf4 = (const uint4*)g_xbf;

    for (int e = t; e < MROWS * 8; e += 256) {
        int r = e >> 3, ch = e & 7;
        *(uint4*)(Xr + r * XSTRIDE + ch * 16) = xbf4[(row0 + r) * 8 + ch];
    }
    if (t < MROWS) {
        #pragma unroll
        for (int q = 0; q < K2; ++q) { skd[t * K2P + q] = finf(); ski[t * K2P + q] = 0; }
        cnt[t] = 0;
        thrS[t] = finf();
    }
    __syncthreads();

    uint32_t afr[2][4][4];
    #pragma unroll
    for (int mi = 0; mi < 2; ++mi)
        #pragma unroll
        for (int ks = 0; ks < 4; ++ks) {
            uint32_t addr = XrB + (m0 + 16 * mi + rsel) * XSTRIDE + (ks * 16 + csel) * 2;
            ldsm_x4(afr[mi][ks][0], afr[mi][ks][1], afr[mi][ks][2], afr[mi][ks][3], addr);
        }

    float thr = finf();
    int   maxpos = 0;
    int   growT = row0 + t;

    int dt = (int)(blockIdx.x >> 2);   // diagonal 256-col tile

    for (int step = 0; step < NPTS / NTILE; ++step) {
        int ct = (step == 0) ? dt : ((step - 1 < dt) ? step - 1 : step);
        int col0 = ct * NTILE;

        for (int e = t; e < NTILE * 8; e += 256) {
            int r = e >> 3, ch = e & 7;
            cpasync16(XcB + r * XSTRIDE + ch * 16, &xbf4[(col0 + r) * 8 + ch]);
        }
        if (t < NTILE) sqc[t] = g_sq[col0 + t];
        asm volatile("cp.async.commit_group;" ::: "memory");
        asm volatile("cp.async.wait_group 0;" ::: "memory");
        __syncthreads();

        bool forcemode = (step == 0);
        bool done = false;
        while (!done) {
            #pragma unroll 1
            for (int h = 0; h < 2; ++h) {
                int hb = h * 128;    // half base within tile
                float acc[2][4][4];
                #pragma unroll
                for (int mi = 0; mi < 2; ++mi)
                    #pragma unroll
                    for (int nt = 0; nt < 4; ++nt)
                        #pragma unroll
                        for (int q = 0; q < 4; ++q) acc[mi][nt][q] = 0.f;

                #pragma unroll
                for (int ks = 0; ks < 4; ++ks) {
                    uint32_t bfr[4][2];
                    #pragma unroll
                    for (int g = 0; g < 2; ++g) {
                        uint32_t r0, r1, r2, r3;
                        uint32_t addr = XcB + (hb + n0 + 16 * g + rsel) * XSTRIDE
                                      + (ks * 16 + csel) * 2;
                        ldsm_x4(r0, r1, r2, r3, addr);
                        bfr[g * 2][0]     = r0; bfr[g * 2][1]     = r2;
                        bfr[g * 2 + 1][0] = r1; bfr[g * 2 + 1][1] = r3;
                    }
                    #pragma unroll
                    for (int mi = 0; mi < 2; ++mi)
                        #pragma unroll
                        for (int nt = 0; nt < 4; ++nt)
                            mma16816(acc[mi][nt], afr[mi][ks], bfr[nt][0], bfr[nt][1]);
                }

                if (!forcemode) {
                    // filter epilogue: quad early-out, push rare survivors
                    #pragma unroll
                    for (int mi = 0; mi < 2; ++mi) {
                        int r0r = m0 + 16 * mi + (lane >> 2);
                        float tr0 = thrS[r0r];
                        float tr1 = thrS[r0r + 8];
                        float trm = fmaxf(tr0, tr1);
                        #pragma unroll
                        for (int nt = 0; nt < 4; ++nt) {
                            int c0 = hb + n0 + nt * 8 + (lane & 3) * 2;
                            float sq0 = sqc[c0], sq1 = sqc[c0 + 1];
                            float d00 = fmaf(-2.f, acc[mi][nt][0], sq0);
                            float d01 = fmaf(-2.f, acc[mi][nt][1], sq1);
                            float d10 = fmaf(-2.f, acc[mi][nt][2], sq0);
                            float d11 = fmaf(-2.f, acc[mi][nt][3], sq1);
                            float mn = fminf(fminf(d00, d01), fminf(d10, d11));
                            if (mn < trm) {
                                int g0 = col0 + c0;
                                #pragma unroll
                                for (int v = 0; v < 4; ++v) {
                                    float d = (v == 0) ? d00 : (v == 1) ? d01
                                             : (v == 2) ? d10 : d11;
                                    int r = r0r + (v >> 1) * 8;
                                    float tr = (v < 2) ? tr0 : tr1;
                                    if (d < tr) {
                                        int gc = g0 + (v & 1);
                                        int i = atomicAdd(&cnt[r], 1);
                                        if (i < CAP) {
                                            bufd[r * CAP + i] = d;
                                            bufc[r * CAP + i] = gc;
                                        } else if (i < CAPX) {
                                            S[r * SSTRIDE + (i - CAP)] = d;
                                            ((int*)(S + r * SSTRIDE))[64 + (i - CAP)] = gc;
                                        }
                                    }
                                }
                            }
                        }
                    }
                } else {
                    // force mode: write S half, owners scan
                    #pragma unroll
                    for (int nt = 0; nt < 4; ++nt) {
                        int c0 = n0 + nt * 8 + (lane & 3) * 2;
                        float2 sq2 = *(float2*)&sqc[hb + c0];
                        #pragma unroll
                        for (int mi = 0; mi < 2; ++mi) {
                            int ra = m0 + 16 * mi + (lane >> 2);
                            float2 v0, v1;
                            v0.x = fmaf(-2.f, acc[mi][nt][0], sq2.x);
                            v0.y = fmaf(-2.f, acc[mi][nt][1], sq2.y);
                            v1.x = fmaf(-2.f, acc[mi][nt][2], sq2.x);
                            v1.y = fmaf(-2.f, acc[mi][nt][3], sq2.y);
                            *(float2*)&S[ra * SSTRIDE + c0]       = v0;
                            *(float2*)&S[(ra + 8) * SSTRIDE + c0] = v1;
                        }
                    }
                    __syncthreads();
                    if (t < MROWS) {
                        #pragma unroll 4
                        for (int c = 0; c < 128; ++c) {
                            float d = S[t * SSTRIDE + c];
                            int g = col0 + hb + c;
                            if (d < thr && g != growT) {
                                skd[t * K2P + maxpos] = d;
                                ski[t * K2P + maxpos] = g;
                                float m = skd[t * K2P]; int mp = 0;
                                #pragma unroll
                                for (int q = 1; q < K2; ++q) {
                                    float v = skd[t * K2P + q];
                                    if (v > m) { m = v; mp = q; }
                                }
                                thr = m; maxpos = mp;
                            }
                        }
                    }
                    __syncthreads();
                }
            }

            if (!forcemode) {
                __syncthreads();   // all pushes visible
                bool over = (t < MROWS) && (cnt[t] > CAPX);
                if (__syncthreads_or(over)) {
                    forcemode = true;   // redo tile exactly (buffer never drained)
                    continue;
                }
                if (t < MROWS) {
                    int n = cnt[t]; if (n > CAPX) n = CAPX;
                    for (int i = 0; i < n; ++i) {
                        float d; int c;
                        if (i < CAP) { d = bufd[t * CAP + i]; c = bufc[t * CAP + i]; }
                        else {
                            d = S[t * SSTRIDE + (i - CAP)];
                            c = ((int*)(S + t * SSTRIDE))[64 + (i - CAP)];
                        }
                        if (d < thr) {
                            skd[t * K2P + maxpos] = d;
                            ski[t * K2P + maxpos] = c;
                            float m = skd[t * K2P]; int mp = 0;
                            #pragma unroll
                            for (int q = 1; q < K2; ++q) {
                                float v = skd[t * K2P + q];
                                if (v > m) { m = v; mp = q; }
                            }
                            thr = m; maxpos = mp;
                        }
                    }
                }
            }
            done = true;
        }

        if (t < MROWS) { thrS[t] = thr; cnt[t] = 0; }
        __syncthreads();
    }

    if (t < MROWS) {
        #pragma unroll
        for (int q = 0; q < K2; ++q)
            g_idx20[growT * K2 + q] = ski[t * K2P + q];
    }
}

// ---------------------------------------------------------------------------
// Kernel 4: exact fp32 rerank of 20 candidates -> true top-16. 1 warp / row.
// ---------------------------------------------------------------------------
__global__ void rerank_kernel(const float* __restrict__ x) {
    __shared__ float xr[8][CDIM];
    __shared__ int   sc[8][K2];
    __shared__ float sd[8][K2];
    int w = threadIdx.x >> 5, lane = threadIdx.x & 31;
    int row = blockIdx.x * 8 + w;

    xr[w][lane]      = x[row * CDIM + lane];
    xr[w][32 + lane] = x[row * CDIM + 32 + lane];
    if (lane < K2) sc[w][lane] = g_idx20[row * K2 + lane];
    __syncwarp();

    #pragma unroll 4
    for (int c = 0; c < K2; ++c) {
        int cand = sc[w][c];
        float v = x[cand * CDIM + lane] * xr[w][lane]
                + x[cand * CDIM + 32 + lane] * xr[w][32 + lane];
        #pragma unroll
        for (int o = 16; o; o >>= 1) v += __shfl_xor_sync(0xffffffffu, v, o);
        if (lane == 0) sd[w][c] = fmaf(-2.0f, v, g_sq[cand]);
    }
    __syncwarp();

    float d = (lane < K2) ? sd[w][lane] : finf();
    int cand = (lane < K2) ? sc[w][lane] : -1;
    unsigned act = 0xFFFFFu;
    #pragma unroll
    for (int rep = 0; rep < K2 - KNN; ++rep) {
        float dm = ((act >> lane) & 1) ? d : -finf();
        float m = dm; int am = lane;
        #pragma unroll
        for (int o = 16; o; o >>= 1) {
            float om = __shfl_xor_sync(0xffffffffu, m, o);
            int   oa = __shfl_xor_sync(0xffffffffu, am, o);
            if (om > m || (om == m && oa < am)) { m = om; am = oa; }
        }
        act &= ~(1u << am);
    }
    if ((act >> lane) & 1) {
        int pos = __popc(act & ((1u << lane) - 1u));
        g_idx[row * KNN + pos] = cand;
    }
}

// ---------------------------------------------------------------------------
// Kernel 5: out = relu(A[i] + max_j B[idx[i,j]]) + fused transpose
// ---------------------------------------------------------------------------
__global__ void out_kernel(float* __restrict__ y) {
    __shared__ int   nbr[4][KNN];
    __shared__ float smv[4][OUTC];
    int t  = threadIdx.x;
    int i0 = blockIdx.x * 4;

    if (t < 4 * KNN) nbr[t >> 4][t & 15] = g_idx[i0 * KNN + t];
    __syncthreads();

    #pragma unroll
    for (int il = 0; il < 4; ++il) {
        int i = i0 + il;
        float m = -finf();
        #pragma unroll
        for (int j = 0; j < KNN; ++j)
            m = fmaxf(m, g_B[nbr[il][j] * OUTC + t]);
        float v = g_A[i * OUTC + t] + m;
        smv[il][t] = fmaxf(v, 0.f);
    }
    __syncthreads();

    for (int e = t; e < 4 * OUTC; e += 256) {
        int c = e & 63;
        int rr = (e >> 6) & 3;
        int il = e >> 8;
        y[i0 * OUTC + e] = smv[il][c * 4 + rr];
    }
}

// ---------------------------------------------------------------------------
extern "C" void kernel_launch(void* const* d_in, const int* in_sizes, int n_in,
                              void* d_out, int out_size) {
    const float* x = (const float*)d_in[0];
    const float* W = (const float*)d_in[1];
    const float* b = (const float*)d_in[2];
    float* y = (float*)d_out;

    static bool attr_done = false;
    if (!attr_done) {
        cudaFuncSetAttribute(knn_tc_kernel,
                             cudaFuncAttributeMaxDynamicSharedMemorySize, KNN_SMEM);
        attr_done = true;
    }

    prep_kernel<<<NPTS * 32 / 256, 256>>>(x);
    gemmAB_kernel<<<NPTS / 8, 256>>>(x, W, b);
    knn_tc_kernel<<<NPTS / MROWS, 256, KNN_SMEM>>>();
    rerank_kernel<<<NPTS / 8, 256>>>(x);
    out_kernel<<<NPTS / 4, 256>>>(y);
}